// round 5
// baseline (speedup 1.0000x reference)
#include <cuda_runtime.h>

// Depth-4 path signature, C=10, L=512. Single fused kernel:
//   - 2 chunks per batch, CTA pair (b,0) and (b,1), 512 threads each.
//   - Register-only packed-f32x2 Chen scan (thread t<500 owns rows t, t+500).
//   - c=0 writes its partial to g_part and releases a flag.
//   - c=1 keeps its partial in registers/smem, acquire-spins on the flag,
//     then performs the Chen combine and writes the final output.
// Grid = 128 CTAs < 148 SMs -> one wave, spin is deadlock-free.

#define SIG_C 10
#define SIG_L 512
#define SIG_NSTEP 511
#define SIG_OUT 11110
#define SIG_MAXB 128
#define CHUNK0 256

typedef unsigned long long u64;

__device__ __align__(16) float g_part[SIG_MAXB * SIG_OUT];
__device__ int g_flag[SIG_MAXB];   // zero-initialized; self-resetting

__device__ __forceinline__ u64 ffma2(u64 a, u64 b, u64 c) {
    u64 d; asm("fma.rn.f32x2 %0, %1, %2, %3;" : "=l"(d) : "l"(a), "l"(b), "l"(c)); return d;
}
__device__ __forceinline__ u64 fmul2(u64 a, u64 b) {
    u64 d; asm("mul.rn.f32x2 %0, %1, %2;" : "=l"(d) : "l"(a), "l"(b)); return d;
}
__device__ __forceinline__ u64 fadd2(u64 a, u64 b) {
    u64 d; asm("add.rn.f32x2 %0, %1, %2;" : "=l"(d) : "l"(a), "l"(b)); return d;
}
__device__ __forceinline__ u64 pack2(float lo, float hi) {
    u64 d; asm("mov.b64 %0, {%1, %2};" : "=l"(d) : "f"(lo), "f"(hi)); return d;
}
__device__ __forceinline__ void unpack2(u64 a, float& lo, float& hi) {
    asm("mov.b64 {%0, %1}, %2;" : "=f"(lo), "=f"(hi) : "l"(a));
}

__global__ __launch_bounds__(512, 1)
void sig_fused_kernel(const float* __restrict__ path, float* __restrict__ out) {
    __shared__ __align__(16) float dxs[CHUNK0 * 12];
    __shared__ __align__(16) float Bl1[10];
    __shared__ __align__(16) float Bl2[100];
    __shared__ __align__(16) float Bl3[1000];

    const int b = blockIdx.x >> 1;
    const int c = blockIdx.x & 1;
    const int start = c ? CHUNK0 : 0;
    const int n = c ? (SIG_NSTEP - CHUNK0) : CHUNK0;   // 255 : 256
    const int tid = threadIdx.x;
    const float* prow = path + (size_t)b * SIG_L * SIG_C + (size_t)start * SIG_C;

    for (int i = tid; i < n * SIG_C; i += 512) {
        int t = i / SIG_C;
        int cc = i - t * SIG_C;
        dxs[t * 12 + cc] = prow[(t + 1) * SIG_C + cc] - prow[t * SIG_C + cc];
    }
    __syncthreads();

    const bool active = (tid < 500);
    const int i1 = (tid / 100) % 5;
    const int i2 = (tid / 10) % 10;
    const int i3 = tid % 10;

    const u64 c1_2  = pack2(0.5f, 0.5f);
    const u64 c1_6  = pack2(1.0f / 6.0f, 1.0f / 6.0f);
    const u64 c1_24 = pack2(1.0f / 24.0f, 1.0f / 24.0f);

    u64 l1v2 = 0, l2v2 = 0, l3_2 = 0;
    u64 l4lo[5], l4hi[5];
#pragma unroll
    for (int j = 0; j < 5; ++j) { l4lo[j] = 0; l4hi[j] = 0; }

    if (active) {
        // ---- init with exp(dx_0) ----
        {
            float Bv = dxs[i2], Cv = dxs[i3];
            u64 A2 = pack2(dxs[i1], dxs[i1 + 5]);
            float d23 = Bv * Cv;
            u64 d23_2 = pack2(d23, d23);
            u64 B2 = pack2(Bv, Bv);
            l1v2 = A2;
            l2v2 = fmul2(fmul2(A2, B2), c1_2);
            l3_2 = fmul2(fmul2(A2, d23_2), c1_6);
            u64 c4 = fmul2(l3_2, pack2(0.25f, 0.25f));
            float clo, chi; unpack2(c4, clo, chi);
            u64 clo2 = pack2(clo, clo), chi2 = pack2(chi, chi);
            ulonglong2 va = *reinterpret_cast<const ulonglong2*>(dxs);
            ulonglong2 vb = *reinterpret_cast<const ulonglong2*>(dxs + 4);
            u64 vc = *reinterpret_cast<const u64*>(dxs + 8);
            l4lo[0] = fmul2(clo2, va.x); l4hi[0] = fmul2(chi2, va.x);
            l4lo[1] = fmul2(clo2, va.y); l4hi[1] = fmul2(chi2, va.y);
            l4lo[2] = fmul2(clo2, vb.x); l4hi[2] = fmul2(chi2, vb.x);
            l4lo[3] = fmul2(clo2, vb.y); l4hi[3] = fmul2(chi2, vb.y);
            l4lo[4] = fmul2(clo2, vc);   l4hi[4] = fmul2(chi2, vc);
        }

        // ---- barrier-free packed scan ----
        const float* base = dxs + 12;
#pragma unroll 4
        for (int t = 1; t < n; ++t) {
            float A_lo = base[i1];
            float A_hi = base[i1 + 5];
            float Bv = base[i2];
            float Cv = base[i3];
            ulonglong2 va = *reinterpret_cast<const ulonglong2*>(base);
            ulonglong2 vb = *reinterpret_cast<const ulonglong2*>(base + 4);
            u64 vc = *reinterpret_cast<const u64*>(base + 8);
            base += 12;

            float d23 = Bv * Cv;
            u64 A2 = pack2(A_lo, A_hi);
            u64 d23_2 = pack2(d23, d23);
            u64 C2 = pack2(Cv, Cv);
            u64 B2 = pack2(Bv, Bv);
            u64 t1 = fmul2(A2, d23_2);
            u64 uu = fmul2(l2v2, C2);
            u64 vv = fmul2(l1v2, d23_2);
            u64 coef = ffma2(c1_24, t1, ffma2(c1_2, uu, ffma2(c1_6, vv, l3_2)));
            l3_2 = ffma2(c1_6, t1, ffma2(c1_2, vv, fadd2(l3_2, uu)));
            l2v2 = ffma2(ffma2(c1_2, A2, l1v2), B2, l2v2);
            l1v2 = fadd2(l1v2, A2);

            float clo, chi; unpack2(coef, clo, chi);
            u64 clo2 = pack2(clo, clo), chi2 = pack2(chi, chi);
            l4lo[0] = ffma2(clo2, va.x, l4lo[0]); l4hi[0] = ffma2(chi2, va.x, l4hi[0]);
            l4lo[1] = ffma2(clo2, va.y, l4lo[1]); l4hi[1] = ffma2(chi2, va.y, l4hi[1]);
            l4lo[2] = ffma2(clo2, vb.x, l4lo[2]); l4hi[2] = ffma2(chi2, vb.x, l4hi[2]);
            l4lo[3] = ffma2(clo2, vb.y, l4lo[3]); l4hi[3] = ffma2(chi2, vb.y, l4hi[3]);
            l4lo[4] = ffma2(clo2, vc,   l4lo[4]); l4hi[4] = ffma2(chi2, vc,   l4hi[4]);
        }
    }

    float lo, hi;

    if (c == 0) {
        // ---- producer: write partial A to g_part, release flag ----
        float* dst = g_part + (size_t)b * SIG_OUT;
        if (active) {
            if (i2 == 0 && i3 == 0) {
                unpack2(l1v2, lo, hi);
                dst[i1] = lo; dst[i1 + 5] = hi;
            }
            if (i3 == 0) {
                unpack2(l2v2, lo, hi);
                dst[10 + i1 * 10 + i2] = lo;
                dst[10 + (i1 + 5) * 10 + i2] = hi;
            }
            unpack2(l3_2, lo, hi);
            dst[110 + tid] = lo;
            dst[110 + tid + 500] = hi;
            u64* d4lo = reinterpret_cast<u64*>(dst + 1110 + (size_t)tid * 10);
            u64* d4hi = reinterpret_cast<u64*>(dst + 1110 + (size_t)(tid + 500) * 10);
#pragma unroll
            for (int j = 0; j < 5; ++j) { d4lo[j] = l4lo[j]; d4hi[j] = l4hi[j]; }
        }
        __threadfence();
        __syncthreads();
        if (tid == 0) {
            asm volatile("st.release.gpu.global.b32 [%0], %1;"
                         :: "l"(g_flag + b), "r"(1) : "memory");
        }
        return;
    }

    // ---- consumer: stash B levels 1-3 in smem, spin, combine ----
    if (active) {
        if (i2 == 0 && i3 == 0) {
            unpack2(l1v2, lo, hi);
            Bl1[i1] = lo; Bl1[i1 + 5] = hi;
        }
        if (i3 == 0) {
            unpack2(l2v2, lo, hi);
            Bl2[i1 * 10 + i2] = lo;
            Bl2[(i1 + 5) * 10 + i2] = hi;
        }
        unpack2(l3_2, lo, hi);
        Bl3[tid] = lo;
        Bl3[tid + 500] = hi;
    }
    __syncthreads();

    if (tid == 0) {
        unsigned f;
        do {
            asm volatile("ld.acquire.gpu.global.b32 %0, [%1];"
                         : "=r"(f) : "l"(g_flag + b) : "memory");
        } while (f == 0);
        asm volatile("st.relaxed.gpu.global.b32 [%0], %1;"
                     :: "l"(g_flag + b), "r"(0) : "memory");   // reset for next replay
    }
    __syncthreads();

    const float* a = g_part + (size_t)b * SIG_OUT;
    float* ob = out + (size_t)b * SIG_OUT;

    // levels 1 and 2
    if (tid < 10)  ob[tid] = a[tid] + Bl1[tid];
    if (tid < 100) ob[10 + tid] = a[10 + tid] + Bl2[tid]
                                + a[tid / 10] * Bl1[tid % 10];

    if (active) {
        // shared B pairs for both rows (same i2,i3)
        const u64* B1p  = reinterpret_cast<const u64*>(Bl1);
        const u64* B2p  = reinterpret_cast<const u64*>(Bl2 + i3 * 10);
        const u64* B3p  = reinterpret_cast<const u64*>(Bl3 + i2 * 100 + i3 * 10);
        const float b2s = Bl2[i2 * 10 + i3];   // B2[i2,i3] for level 3
        const float b1s = Bl1[i3];             // B1[i3]    for level 3

#pragma unroll
        for (int half = 0; half < 2; ++half) {
            const int p   = tid + half * 500;
            const int j1  = i1 + half * 5;
            const u64* B4 = half ? l4hi : l4lo;
            float a1 = a[j1];
            float a2 = a[10 + j1 * 10 + i2];
            float a3 = a[110 + p];
            float b3s = Bl3[p];

            ob[110 + p] = a3 + b3s + a1 * b2s + a2 * b1s;

            u64 a1_2 = pack2(a1, a1);
            u64 a2_2 = pack2(a2, a2);
            u64 a3_2 = pack2(a3, a3);
            const u64* A4 = reinterpret_cast<const u64*>(a + 1110 + (size_t)p * 10);
            u64* o4 = reinterpret_cast<u64*>(ob + 1110 + (size_t)p * 10);
#pragma unroll
            for (int j = 0; j < 5; ++j) {
                u64 s = fadd2(A4[j], B4[j]);
                s = ffma2(a3_2, B1p[j], s);
                s = ffma2(a2_2, B2p[j], s);
                s = ffma2(a1_2, B3p[j], s);
                o4[j] = s;
            }
        }
    }
}

extern "C" void kernel_launch(void* const* d_in, const int* in_sizes, int n_in,
                              void* d_out, int out_size) {
    const float* path = (const float*)d_in[0];
    float* out = (float*)d_out;
    int B = in_sizes[0] / (SIG_L * SIG_C);
    if (B > SIG_MAXB) B = SIG_MAXB;
    sig_fused_kernel<<<B * 2, 512>>>(path, out);
}